// round 1
// baseline (speedup 1.0000x reference)
#include <cuda_runtime.h>
#include <cstdint>

#define EPSF 1e-5f

// ---------------- scratch (device globals; no allocation allowed) ----------
__device__ float    g_x0[20000 * 64];
__device__ float    g_tmp[20000 * 256];
__device__ float    g_bufA[20000 * 256];
__device__ float    g_bufB[20000 * 256];
__device__ float    g_nt[20000 * 128];      // edgeconv node term
__device__ unsigned g_mkey[20000 * 128];    // encoded max accumulator
__device__ int      g_deg[20000];
__device__ float    g_dinv[20000];

// ---------------- helpers ---------------------------------------------------
__device__ __forceinline__ unsigned fenc(float f) {
    unsigned b = __float_as_uint(f);
    return (b & 0x80000000u) ? ~b : (b | 0x80000000u);
}
__device__ __forceinline__ float fdec(unsigned u) {
    return (u & 0x80000000u) ? __uint_as_float(u & 0x7fffffffu)
                             : __uint_as_float(~u);
}

// ---------------- degree / norm --------------------------------------------
__global__ void k_zero_i32(int* p, int n) {
    int i = blockIdx.x * blockDim.x + threadIdx.x;
    if (i < n) p[i] = 0;
}
__global__ void k_zero_u32(unsigned* p, int n) {
    int i = blockIdx.x * blockDim.x + threadIdx.x;
    if (i < n) p[i] = 0u;
}
__global__ void k_count_deg(const int* __restrict__ dst, int E) {
    int i = blockIdx.x * blockDim.x + threadIdx.x;
    if (i < E) atomicAdd(&g_deg[dst[i]], 1);
}
__global__ void k_dinv(int n) {
    int i = blockIdx.x * blockDim.x + threadIdx.x;
    if (i < n) g_dinv[i] = rsqrtf((float)(g_deg[i] + 1));
}

// ---------------- generic tiled GEMM (BM=64, BK=32, 256 thr) ----------------
// C[M,Nout] = op(A)[M,K] @ B[K,Nout]; BNR: A' = relu(A*scale + shift) with
// per-channel BN stats (first-half channels of an EdgeConv layer).
template <int BN, bool BNR>
__global__ __launch_bounds__(256) void k_gemm(
    const float* __restrict__ A, const float* __restrict__ B,
    float* __restrict__ C, int M, int K, int Nout,
    const float* __restrict__ gamma, const float* __restrict__ beta,
    const float* __restrict__ mean, const float* __restrict__ var)
{
    constexpr int TN = BN / 16;
    __shared__ float As[32][68];
    __shared__ float Bs[32][BN];
    __shared__ float s_sc[BNR ? 256 : 4];
    __shared__ float s_sh[BNR ? 256 : 4];

    const int tid = threadIdx.x;
    const int m0 = blockIdx.x * 64;
    const int n0 = blockIdx.y * BN;

    if (BNR) {
        for (int k = tid; k < K; k += 256) {
            float sc = gamma[k] * rsqrtf(var[k] + EPSF);
            s_sc[k] = sc;
            s_sh[k] = beta[k] - mean[k] * sc;
        }
        __syncthreads();
    }

    const int tx = tid & 15, ty = tid >> 4;
    float acc[4][TN];
#pragma unroll
    for (int i = 0; i < 4; i++)
#pragma unroll
        for (int j = 0; j < TN; j++) acc[i][j] = 0.f;

    for (int kt = 0; kt < K; kt += 32) {
#pragma unroll
        for (int it = 0; it < 2; it++) {
            int slot = tid + it * 256;
            int r = slot >> 3, q = slot & 7;
            int m = m0 + r;
            float4 v = make_float4(0.f, 0.f, 0.f, 0.f);
            if (m < M) v = *(const float4*)&A[(size_t)m * K + kt + q * 4];
            if (BNR) {
                int kb = kt + q * 4;
                v.x = fmaxf(v.x * s_sc[kb + 0] + s_sh[kb + 0], 0.f);
                v.y = fmaxf(v.y * s_sc[kb + 1] + s_sh[kb + 1], 0.f);
                v.z = fmaxf(v.z * s_sc[kb + 2] + s_sh[kb + 2], 0.f);
                v.w = fmaxf(v.w * s_sc[kb + 3] + s_sh[kb + 3], 0.f);
            }
            As[q * 4 + 0][r] = v.x;
            As[q * 4 + 1][r] = v.y;
            As[q * 4 + 2][r] = v.z;
            As[q * 4 + 3][r] = v.w;
        }
#pragma unroll
        for (int it = 0; it < BN / 32; it++) {
            int slot = tid + it * 256;
            int row = slot / (BN / 4), c4 = slot % (BN / 4);
            *(float4*)&Bs[row][c4 * 4] =
                *(const float4*)&B[(size_t)(kt + row) * Nout + n0 + c4 * 4];
        }
        __syncthreads();
#pragma unroll
        for (int k = 0; k < 32; k++) {
            float4 a4 = *(const float4*)&As[k][ty * 4];
            float ar[4] = {a4.x, a4.y, a4.z, a4.w};
            float br[TN];
#pragma unroll
            for (int j4 = 0; j4 < TN / 4; j4++) {
                float4 b4 = *(const float4*)&Bs[k][tx * TN + j4 * 4];
                br[j4 * 4 + 0] = b4.x;
                br[j4 * 4 + 1] = b4.y;
                br[j4 * 4 + 2] = b4.z;
                br[j4 * 4 + 3] = b4.w;
            }
#pragma unroll
            for (int i = 0; i < 4; i++)
#pragma unroll
                for (int j = 0; j < TN; j++)
                    acc[i][j] = fmaf(ar[i], br[j], acc[i][j]);
        }
        __syncthreads();
    }
#pragma unroll
    for (int i = 0; i < 4; i++) {
        int m = m0 + ty * 4 + i;
        if (m < M) {
#pragma unroll
            for (int j4 = 0; j4 < TN / 4; j4++) {
                float4 o = make_float4(acc[i][j4 * 4 + 0], acc[i][j4 * 4 + 1],
                                       acc[i][j4 * 4 + 2], acc[i][j4 * 4 + 3]);
                *(float4*)&C[(size_t)m * Nout + n0 + tx * TN + j4 * 4] = o;
            }
        }
    }
}

// ---------------- input projection with per-row weight select ---------------
// rows with m%4==0 use (Wm,bm), others (Wc,bc). K=512, Nout=64.
__global__ __launch_bounds__(256) void k_proj(
    const float* __restrict__ x, const float* __restrict__ Wm,
    const float* __restrict__ bm, const float* __restrict__ Wc,
    const float* __restrict__ bc, float* __restrict__ out, int M)
{
    __shared__ float As[32][68];
    __shared__ float Bm_s[32][64];
    __shared__ float Bc_s[32][64];
    const int tid = threadIdx.x;
    const int m0 = blockIdx.x * 64;
    const int tx = tid & 15, ty = tid >> 4;
    float acc[4][4] = {};

    for (int kt = 0; kt < 512; kt += 32) {
#pragma unroll
        for (int it = 0; it < 2; it++) {
            int slot = tid + it * 256;
            int r = slot >> 3, q = slot & 7;
            int m = m0 + r;
            float4 v = make_float4(0.f, 0.f, 0.f, 0.f);
            if (m < M) v = *(const float4*)&x[(size_t)m * 512 + kt + q * 4];
            As[q * 4 + 0][r] = v.x;
            As[q * 4 + 1][r] = v.y;
            As[q * 4 + 2][r] = v.z;
            As[q * 4 + 3][r] = v.w;
        }
#pragma unroll
        for (int it = 0; it < 2; it++) {
            int slot = tid + it * 256;
            int row = slot >> 4, c4 = slot & 15;
            *(float4*)&Bm_s[row][c4 * 4] =
                *(const float4*)&Wm[(size_t)(kt + row) * 64 + c4 * 4];
            *(float4*)&Bc_s[row][c4 * 4] =
                *(const float4*)&Wc[(size_t)(kt + row) * 64 + c4 * 4];
        }
        __syncthreads();
#pragma unroll
        for (int k = 0; k < 32; k++) {
            float4 a4 = *(const float4*)&As[k][ty * 4];
            float4 bm4 = *(const float4*)&Bm_s[k][tx * 4];
            float4 bc4 = *(const float4*)&Bc_s[k][tx * 4];
            float bmr[4] = {bm4.x, bm4.y, bm4.z, bm4.w};
            float bcr[4] = {bc4.x, bc4.y, bc4.z, bc4.w};
            float ar[4] = {a4.x, a4.y, a4.z, a4.w};
#pragma unroll
            for (int j = 0; j < 4; j++) acc[0][j] = fmaf(ar[0], bmr[j], acc[0][j]);
#pragma unroll
            for (int i = 1; i < 4; i++)
#pragma unroll
                for (int j = 0; j < 4; j++) acc[i][j] = fmaf(ar[i], bcr[j], acc[i][j]);
        }
        __syncthreads();
    }
#pragma unroll
    for (int i = 0; i < 4; i++) {
        int m = m0 + ty * 4 + i;
        if (m < M) {
            const float* bias = (i == 0) ? bm : bc;
#pragma unroll
            for (int j = 0; j < 4; j++)
                out[(size_t)m * 64 + tx * 4 + j] = acc[i][j] + bias[tx * 4 + j];
        }
    }
}

// ---------------- GCN aggregation -------------------------------------------
// out init: bias + self-loop term
__global__ void k_gcn_init(const float* __restrict__ tmp,
                           const float* __restrict__ bias,
                           float* __restrict__ out, int n, int Wd)
{
    int idx = blockIdx.x * blockDim.x + threadIdx.x;
    if (idx < n * Wd) {
        int i = idx / Wd;
        int c = idx - i * Wd;
        float dv = g_dinv[i];
        out[idx] = bias[c] + tmp[idx] * dv * dv;
    }
}
// one warp per edge: out[dst] += tmp[src] * dinv[src]*dinv[dst]
__global__ void k_gcn_edge(const float* __restrict__ tmp,
                           const int* __restrict__ src,
                           const int* __restrict__ dst,
                           float* __restrict__ out, int E, int W4)
{
    int g = blockIdx.x * blockDim.x + threadIdx.x;
    int e = g >> 5, lane = g & 31;
    if (e >= E) return;
    int s = src[e], d = dst[e];
    float coef = g_dinv[s] * g_dinv[d];
    const float4* ts = (const float4*)(tmp + (size_t)s * W4 * 4);
    float4* od = (float4*)(out + (size_t)d * W4 * 4);
    for (int j = lane; j < W4; j += 32) {
        float4 v = ts[j];
        v.x *= coef; v.y *= coef; v.z *= coef; v.w *= coef;
        asm volatile("red.global.add.v4.f32 [%0], {%1,%2,%3,%4};"
                     :: "l"(od + j), "f"(v.x), "f"(v.y), "f"(v.z), "f"(v.w)
                     : "memory");
    }
}

// ---------------- EdgeConv edge term ----------------------------------------
// b_e = relu( (x[src]-x[dst]) * sc2 + sh2 ) @ W_bot ; atomicMax into mkey[dst]
template <int C>
__global__ __launch_bounds__(256) void k_edge_term(
    const float* __restrict__ xf, const int* __restrict__ src,
    const int* __restrict__ dst,
    const float* __restrict__ gamma, const float* __restrict__ beta,
    const float* __restrict__ mean, const float* __restrict__ var,
    const float* __restrict__ W,  // full [2C,128]; rows C..2C-1 used
    unsigned* __restrict__ mkey, int E)
{
    __shared__ float As[32][68];
    __shared__ float Bs[32][128];
    __shared__ float s_sc[C], s_sh[C];
    __shared__ int s_src[64], s_dst[64];
    const int tid = threadIdx.x;

    for (int k = tid; k < C; k += 256) {
        float sc = gamma[C + k] * rsqrtf(var[C + k] + EPSF);
        s_sc[k] = sc;
        s_sh[k] = beta[C + k] - mean[C + k] * sc;
    }
    const int e0 = blockIdx.x * 64;
    if (tid < 64) {
        int e = e0 + tid;
        s_src[tid] = (e < E) ? src[e] : 0;
        s_dst[tid] = (e < E) ? dst[e] : 0;
    }
    __syncthreads();

    const int tx = tid & 15, ty = tid >> 4;
    float acc[4][8] = {};
    const float* Wb = W + (size_t)C * 128;

    for (int kt = 0; kt < C; kt += 32) {
#pragma unroll
        for (int it = 0; it < 2; it++) {
            int slot = tid + it * 256;
            int r = slot >> 3, q = slot & 7;
            const float4 a = *(const float4*)&xf[(size_t)s_src[r] * C + kt + q * 4];
            const float4 b = *(const float4*)&xf[(size_t)s_dst[r] * C + kt + q * 4];
            int kb = kt + q * 4;
            As[q * 4 + 0][r] = fmaxf((a.x - b.x) * s_sc[kb + 0] + s_sh[kb + 0], 0.f);
            As[q * 4 + 1][r] = fmaxf((a.y - b.y) * s_sc[kb + 1] + s_sh[kb + 1], 0.f);
            As[q * 4 + 2][r] = fmaxf((a.z - b.z) * s_sc[kb + 2] + s_sh[kb + 2], 0.f);
            As[q * 4 + 3][r] = fmaxf((a.w - b.w) * s_sc[kb + 3] + s_sh[kb + 3], 0.f);
        }
#pragma unroll
        for (int it = 0; it < 4; it++) {
            int slot = tid + it * 256;
            int row = slot >> 5, c4 = slot & 31;
            *(float4*)&Bs[row][c4 * 4] =
                *(const float4*)&Wb[(size_t)(kt + row) * 128 + c4 * 4];
        }
        __syncthreads();
#pragma unroll
        for (int k = 0; k < 32; k++) {
            float4 a4 = *(const float4*)&As[k][ty * 4];
            float ar[4] = {a4.x, a4.y, a4.z, a4.w};
            float4 b0 = *(const float4*)&Bs[k][tx * 8];
            float4 b1 = *(const float4*)&Bs[k][tx * 8 + 4];
            float br[8] = {b0.x, b0.y, b0.z, b0.w, b1.x, b1.y, b1.z, b1.w};
#pragma unroll
            for (int i = 0; i < 4; i++)
#pragma unroll
                for (int j = 0; j < 8; j++)
                    acc[i][j] = fmaf(ar[i], br[j], acc[i][j]);
        }
        __syncthreads();
    }
#pragma unroll
    for (int i = 0; i < 4; i++) {
        int el = ty * 4 + i;
        int e = e0 + el;
        if (e < E) {
            unsigned* mp = mkey + (size_t)s_dst[el] * 128 + tx * 8;
#pragma unroll
            for (int j = 0; j < 8; j++) atomicMax(mp + j, fenc(acc[i][j]));
        }
    }
}

// h[i] = deg>0 ? node_term + decode(max) : 0
__global__ void k_ec_final(const float* __restrict__ a,
                           const unsigned* __restrict__ mk,
                           float* __restrict__ h, int n)
{
    int idx = blockIdx.x * blockDim.x + threadIdx.x;
    if (idx < n * 128) {
        int i = idx >> 7;
        h[idx] = (g_deg[i] > 0) ? (a[idx] + fdec(mk[idx])) : 0.f;
    }
}

// ---------------- final FC ---------------------------------------------------
__global__ void k_final(const float* __restrict__ h, const float* __restrict__ Wfc,
                        const float* __restrict__ bfc, float* __restrict__ out, int n)
{
    int g = blockIdx.x * blockDim.x + threadIdx.x;
    int w = g >> 5, lane = g & 31;
    if (w >= n) return;
    float4 a = *(const float4*)&h[(size_t)w * 128 + lane * 4];
    float4 ww = *(const float4*)&Wfc[lane * 4];
    float s = a.x * ww.x + a.y * ww.y + a.z * ww.z + a.w * ww.w;
#pragma unroll
    for (int o = 16; o > 0; o >>= 1) s += __shfl_xor_sync(0xffffffffu, s, o);
    if (lane == 0) out[w] = s + bfc[0];
}

// ---------------- launch ------------------------------------------------------
extern "C" void kernel_launch(void* const* d_in, const int* in_sizes, int n_in,
                              void* d_out, int out_size)
{
    const float* x   = (const float*)d_in[0];
    const int*   ei  = (const int*)d_in[1];
    const float* Wm  = (const float*)d_in[2];
    const float* bm  = (const float*)d_in[3];
    const float* Wc  = (const float*)d_in[4];
    const float* bc  = (const float*)d_in[5];
    const float* Wg1 = (const float*)d_in[6];
    const float* bg1 = (const float*)d_in[7];
    const float* Wg2 = (const float*)d_in[8];
    const float* bg2 = (const float*)d_in[9];
    const float* Wg3 = (const float*)d_in[10];
    const float* bg3 = (const float*)d_in[11];
    const float* e1g = (const float*)d_in[12];
    const float* e1b = (const float*)d_in[13];
    const float* e1m = (const float*)d_in[14];
    const float* e1v = (const float*)d_in[15];
    const float* e1W = (const float*)d_in[16];
    const float* e2g = (const float*)d_in[17];
    const float* e2b = (const float*)d_in[18];
    const float* e2m = (const float*)d_in[19];
    const float* e2v = (const float*)d_in[20];
    const float* e2W = (const float*)d_in[21];
    const float* e3g = (const float*)d_in[22];
    const float* e3b = (const float*)d_in[23];
    const float* e3m = (const float*)d_in[24];
    const float* e3v = (const float*)d_in[25];
    const float* e3W = (const float*)d_in[26];
    const float* Wfc = (const float*)d_in[27];
    const float* bfc = (const float*)d_in[28];
    float* out = (float*)d_out;

    const int n = in_sizes[0] / 512;
    const int E = in_sizes[1] / 2;
    const int* src = ei;
    const int* dst = ei + E;

    float *p_x0, *p_tmp, *p_bufA, *p_bufB, *p_nt, *p_dinv;
    unsigned* p_mkey;
    int* p_deg;
    cudaGetSymbolAddress((void**)&p_x0, g_x0);
    cudaGetSymbolAddress((void**)&p_tmp, g_tmp);
    cudaGetSymbolAddress((void**)&p_bufA, g_bufA);
    cudaGetSymbolAddress((void**)&p_bufB, g_bufB);
    cudaGetSymbolAddress((void**)&p_nt, g_nt);
    cudaGetSymbolAddress((void**)&p_mkey, g_mkey);
    cudaGetSymbolAddress((void**)&p_deg, g_deg);
    cudaGetSymbolAddress((void**)&p_dinv, g_dinv);

    const int mb = (n + 63) / 64;
    const int THR = 256;
    auto blks = [&](int work) { return (work + THR - 1) / THR; };

    // degrees + normalization
    k_zero_i32<<<blks(n), THR>>>(p_deg, n);
    k_count_deg<<<blks(E), THR>>>(dst, E);
    k_dinv<<<blks(n), THR>>>(n);

    // input projection (row-select Wm/Wc)
    k_proj<<<mb, THR>>>(x, Wm, bm, Wc, bc, p_x0, n);

    // GCN 1: 64 -> 128
    k_gemm<128, false><<<dim3(mb, 1), THR>>>(p_x0, Wg1, p_tmp, n, 64, 128,
                                             nullptr, nullptr, nullptr, nullptr);
    k_gcn_init<<<blks(n * 128), THR>>>(p_tmp, bg1, p_bufA, n, 128);
    k_gcn_edge<<<(E + 7) / 8, THR>>>(p_tmp, src, dst, p_bufA, E, 32);

    // GCN 2: 128 -> 128
    k_gemm<128, false><<<dim3(mb, 1), THR>>>(p_bufA, Wg2, p_tmp, n, 128, 128,
                                             nullptr, nullptr, nullptr, nullptr);
    k_gcn_init<<<blks(n * 128), THR>>>(p_tmp, bg2, p_bufB, n, 128);
    k_gcn_edge<<<(E + 7) / 8, THR>>>(p_tmp, src, dst, p_bufB, E, 32);

    // GCN 3: 128 -> 256
    k_gemm<128, false><<<dim3(mb, 2), THR>>>(p_bufB, Wg3, p_tmp, n, 128, 256,
                                             nullptr, nullptr, nullptr, nullptr);
    k_gcn_init<<<blks(n * 256), THR>>>(p_tmp, bg3, p_bufA, n, 256);
    k_gcn_edge<<<(E + 7) / 8, THR>>>(p_tmp, src, dst, p_bufA, E, 64);

    // EdgeConv 1: C=256 -> 128   (in: p_bufA, out: p_bufB)
    k_gemm<128, true><<<dim3(mb, 1), THR>>>(p_bufA, e1W, p_nt, n, 256, 128,
                                            e1g, e1b, e1m, e1v);
    k_zero_u32<<<blks(n * 128), THR>>>(p_mkey, n * 128);
    k_edge_term<256><<<(E + 63) / 64, THR>>>(p_bufA, src, dst, e1g, e1b, e1m,
                                             e1v, e1W, p_mkey, E);
    k_ec_final<<<blks(n * 128), THR>>>(p_nt, p_mkey, p_bufB, n);

    // EdgeConv 2: C=128 -> 128   (in: p_bufB, out: p_tmp)
    k_gemm<128, true><<<dim3(mb, 1), THR>>>(p_bufB, e2W, p_nt, n, 128, 128,
                                            e2g, e2b, e2m, e2v);
    k_zero_u32<<<blks(n * 128), THR>>>(p_mkey, n * 128);
    k_edge_term<128><<<(E + 63) / 64, THR>>>(p_bufB, src, dst, e2g, e2b, e2m,
                                             e2v, e2W, p_mkey, E);
    k_ec_final<<<blks(n * 128), THR>>>(p_nt, p_mkey, p_tmp, n);

    // EdgeConv 3: C=128 -> 128   (in: p_tmp, out: p_bufA)
    k_gemm<128, true><<<dim3(mb, 1), THR>>>(p_tmp, e3W, p_nt, n, 128, 128,
                                            e3g, e3b, e3m, e3v);
    k_zero_u32<<<blks(n * 128), THR>>>(p_mkey, n * 128);
    k_edge_term<128><<<(E + 63) / 64, THR>>>(p_tmp, src, dst, e3g, e3b, e3m,
                                             e3v, e3W, p_mkey, E);
    k_ec_final<<<blks(n * 128), THR>>>(p_nt, p_mkey, p_bufA, n);

    // final FC: [N,128] @ [128,1] + b
    k_final<<<blks(n * 32), THR>>>(p_bufA, Wfc, bfc, out, n);
}